// round 12
// baseline (speedup 1.0000x reference)
#include <cuda_runtime.h>
#include <cuda_fp16.h>
#include <cstdint>

// ---------------- problem constants ----------------
#define NBODY     10
#define NPAIRS    90
#define HID       128
#define TILE      128
#define SELF_ROWS 81920
#define INT_ROWS  737280
#define SELF_TILES (SELF_ROWS / TILE)   // 640
#define INT_TILES  (INT_ROWS / TILE)    // 5760
#define NCTA      148
#define NTHREADS  512                   // 2 tile-streams of 256 threads
#define SW        72                    // Aw row stride in words (72%32=8, conflict-free)

// smem byte offsets
#define OFF_W1T   0          // 128 x SW half2-words                 36864 B
#define OFF_A0    36864      // stream 0 H0: 128 x SW half2-words    36864 B
#define OFF_A1    73728      // stream 1                             36864 B
#define OFF_P0    110592     // stream partials 8KB each
#define OFF_P1    118784
#define OFF_I0    126976     // stream packed inp: 128 x 8 words     4096 B each
#define OFF_I1    131072
#define OFF_W0H   135168     // W0 fp16 B-layout (+bias in word 7): 128 x 8 words
#define OFF_W2H   139264     // W2 fp16 B-layout: 8 x 64 words       2048 B
#define OFF_B1    141312     // 128 fp32
#define OFF_B2    141824     // 4 fp32 (+pad)
#define SMEM_TOTAL 141856

#define ONE_H2    0x00003C00u   // half2 (1.0, 0.0)

__device__ float g_scratch[INT_ROWS * 4];
__device__ unsigned int g_bar_count = 0;
__device__ unsigned int g_bar_sense = 0;

// ---------------- helpers ----------------
__device__ __forceinline__ float softplus_f(float x) {
    float e = __expf(-fabsf(x));
    return fmaxf(x, 0.0f) + __logf(1.0f + e);
}
// permute words within each 8-group so (u, u+4) are adjacent -> uint2 loads
__device__ __forceinline__ int pos8(int c) {
    return (c & ~7) | ((c & 3) << 1) | ((c >> 2) & 1);
}
__device__ __forceinline__ uint32_t packh2(float a, float b) {
    __half2 v = __floats2half2_rn(a, b);
    return *(uint32_t*)&v;
}
__device__ __forceinline__ void mma_f16(float* c, uint32_t a0, uint32_t a1,
                                        uint32_t a2, uint32_t a3,
                                        uint32_t b0, uint32_t b1) {
    asm("mma.sync.aligned.m16n8k16.row.col.f32.f16.f16.f32 "
        "{%0,%1,%2,%3}, {%4,%5,%6,%7}, {%8,%9}, {%0,%1,%2,%3};"
        : "+f"(c[0]), "+f"(c[1]), "+f"(c[2]), "+f"(c[3])
        : "r"(a0), "r"(a1), "r"(a2), "r"(a3), "r"(b0), "r"(b1));
}

// ---------------- two-phase persistent fused MLP + in-kernel reduce ----------------
__global__ __launch_bounds__(NTHREADS, 1)
void mlp_all(const float* __restrict__ z,
             const float* __restrict__ fW0, const float* __restrict__ fb0,
             const float* __restrict__ fW1, const float* __restrict__ fb1,
             const float* __restrict__ fW2, const float* __restrict__ fb2,
             const float* __restrict__ iW0, const float* __restrict__ ib0,
             const float* __restrict__ iW1, const float* __restrict__ ib1,
             const float* __restrict__ iW2, const float* __restrict__ ib2,
             float* __restrict__ out_self)
{
    extern __shared__ __align__(16) char smem[];
    uint32_t* W1w = (uint32_t*)(smem + OFF_W1T);
    uint32_t* W0h = (uint32_t*)(smem + OFF_W0H);
    uint32_t* W2h = (uint32_t*)(smem + OFF_W2H);
    float*  b1s = (float*)(smem + OFF_B1);
    float*  b2s = (float*)(smem + OFF_B2);

    const int tid  = threadIdx.x;
    const int wg   = tid >> 8;            // tile stream 0/1
    const int wt   = tid & 255;
    const int w8   = wt >> 5;             // warp in stream: 0..7
    const int lane = tid & 31;
    const int g    = lane >> 2;
    const int j    = lane & 3;
    const int mi   = w8 >> 2;             // rows mi*64..+63
    const int ni   = w8 & 3;              // cols ni*32..+31

    uint32_t* Aw = (uint32_t*)(smem + OFF_A0 + wg * 36864);
    uint32_t* Iw = (uint32_t*)(smem + OFF_I0 + wg * 4096);
    float*    P  = (float*)(smem + OFF_P0 + wg * 8192);
    const int wbar = 1 + wg;

    // capture barrier sense for this launch
    __shared__ unsigned int sense0;
    if (tid == 0) sense0 = *(volatile unsigned int*)&g_bar_sense;
    __syncthreads();

    const int r0 = mi * 64, n0 = ni * 32;

    // Aw store positions for layer-0 output (word u = ni*16 + nt*4 + j)
    int apos[4];
    #pragma unroll
    for (int nt = 0; nt < 4; nt++) {
        int uu = ni * 16 + nt * 4 + j;
        apos[nt] = (uu & ~7) | ((uu & 3) << 1) | ((uu >> 2) & 1);
    }

    #pragma unroll 1
    for (int phase = 0; phase < 2; phase++) {
        const bool isSelf = (phase == 1);
        const float* W0 = isSelf ? fW0 : iW0;
        const float* b0 = isSelf ? fb0 : ib0;
        const float* W1 = isSelf ? fW1 : iW1;
        const float* b1 = isSelf ? fb1 : ib1;
        const float* W2 = isSelf ? fW2 : iW2;
        const float* b2 = isSelf ? fb2 : ib2;
        float* out = isSelf ? out_self : g_scratch;
        const int ntiles = isSelf ? SELF_TILES : INT_TILES;
        const int NIN = isSelf ? 4 : 6;

        // ---- stage weights for this phase ----
        for (int i = tid; i < 64 * HID; i += NTHREADS) {
            int uu = i >> 7, n = i & 127;
            W1w[n * SW + pos8(uu)] = packh2(W1[(2 * uu) * HID + n],
                                            W1[(2 * uu + 1) * HID + n]);
        }
        // W0h: word(n,u) = (W0[2u][n], W0[2u+1][n]) zero-padded; word 7 = (b0[n], 0)
        for (int i = tid; i < 8 * HID; i += NTHREADS) {
            int n = i >> 3, uu = i & 7;
            float a, b;
            if (uu == 7) { a = b0[n]; b = 0.0f; }
            else {
                a = (2 * uu     < NIN) ? W0[(2 * uu)     * HID + n] : 0.0f;
                b = (2 * uu + 1 < NIN) ? W0[(2 * uu + 1) * HID + n] : 0.0f;
            }
            W0h[n * 8 + pos8(uu)] = packh2(a, b);
        }
        // W2h: word(n,u) = (W2[2u][n], W2[2u+1][n]) n<4 else 0, at n*64+pos8(u)
        for (int i = tid; i < 512; i += NTHREADS) {
            int n = i >> 6, uu = i & 63;
            float a = (n < 4) ? W2[(2 * uu)     * 4 + n] : 0.0f;
            float b = (n < 4) ? W2[(2 * uu + 1) * 4 + n] : 0.0f;
            W2h[n * 64 + pos8(uu)] = packh2(a, b);
        }
        if (tid < HID) b1s[tid] = b1[tid];
        if (tid < 4) b2s[tid] = b2[tid];
        __syncthreads();

        const float4 b2v = *(const float4*)b2s;
        // tile-invariant fragments
        uint2 w0f[4];
        #pragma unroll
        for (int nt = 0; nt < 4; nt++)
            w0f[nt] = *(const uint2*)&W0h[(n0 + nt * 8 + g) * 8 + 2 * j];
        uint2 w2f[2];
        #pragma unroll
        for (int q = 0; q < 2; q++)
            w2f[q] = *(const uint2*)&W2h[g * 64 + ni * 16 + 8 * q + 2 * j];

        // self phase: reversed stream mapping balances per-CTA totals at <=44 tiles
        int s0 = blockIdx.x * 2 + wg;
        if (isSelf) s0 = gridDim.x * 2 - 1 - s0;

        for (int t = s0; t < ntiles; t += gridDim.x * 2) {
            const int rowBase = t * TILE;

            // ---- build 128 packed input rows (fp16); k14 = 1.0 (bias lane) ----
            if (wt < 128) {
                int grow = rowBase + wt;
                uint32_t wA, wB, wC;
                if (isSelf) {
                    float4 zz = ((const float4*)z)[grow];
                    wA = packh2(zz.x, zz.y); wB = packh2(zz.z, zz.w); wC = 0u;
                } else {
                    int n   = grow / NPAIRS;
                    int pr  = grow - n * NPAIRS;
                    int rec = pr / (NBODY - 1);
                    int sr  = pr - rec * (NBODY - 1);
                    int snd = sr + (sr >= rec ? 1 : 0);
                    float4 zr = ((const float4*)z)[n * NBODY + rec];
                    float4 zs = ((const float4*)z)[n * NBODY + snd];
                    wA = packh2(zr.x - zs.x, zr.y - zs.y);
                    wB = packh2(zr.z, zr.w);
                    wC = packh2(zs.z, zs.w);
                }
                int base = wt * 8;
                *(uint2*)&Iw[base + 0] = make_uint2(wA, 0u);
                *(uint2*)&Iw[base + 2] = make_uint2(wB, 0u);
                *(uint2*)&Iw[base + 4] = make_uint2(wC, 0u);
                *(uint2*)&Iw[base + 6] = make_uint2(0u, ONE_H2);
            }
            asm volatile("bar.sync %0, 256;" :: "r"(wbar) : "memory");

            float c[4][4][4];

            // ---- layer 0 via m16n8k16: preact = inp @ W0 (+b0 via k14) ----
            #pragma unroll
            for (int mt = 0; mt < 4; mt++)
                #pragma unroll
                for (int nt = 0; nt < 4; nt++)
                    #pragma unroll
                    for (int q = 0; q < 4; q++) c[mt][nt][q] = 0.0f;
            #pragma unroll
            for (int mt = 0; mt < 4; mt++) {
                uint2 lo = *(const uint2*)&Iw[(r0 + mt * 16 + g) * 8 + 2 * j];
                uint2 hi = *(const uint2*)&Iw[(r0 + mt * 16 + 8 + g) * 8 + 2 * j];
                #pragma unroll
                for (int nt = 0; nt < 4; nt++)
                    mma_f16(c[mt][nt], lo.x, hi.x, lo.y, hi.y,
                            w0f[nt].x, w0f[nt].y);
            }
            // softplus + pack + store H0 slice (rows r0..r0+63, cols n0..n0+31)
            #pragma unroll
            for (int mt = 0; mt < 4; mt++)
                #pragma unroll
                for (int nt = 0; nt < 4; nt++) {
                    float p0 = softplus_f(c[mt][nt][0]);
                    float p1 = softplus_f(c[mt][nt][1]);
                    float p2 = softplus_f(c[mt][nt][2]);
                    float p3 = softplus_f(c[mt][nt][3]);
                    Aw[(r0 + mt * 16 + g) * SW + apos[nt]]     = packh2(p0, p1);
                    Aw[(r0 + mt * 16 + 8 + g) * SW + apos[nt]] = packh2(p2, p3);
                }
            asm volatile("bar.sync %0, 256;" :: "r"(wbar) : "memory");

            // ---- layer 1: 64x32 warp tile, m16n8k16 fp16, 8 k-steps (R8-exact) ----
            #pragma unroll
            for (int mt = 0; mt < 4; mt++)
                #pragma unroll
                for (int nt = 0; nt < 4; nt++)
                    #pragma unroll
                    for (int q = 0; q < 4; q++) c[mt][nt][q] = 0.0f;

            #pragma unroll 1
            for (int s = 0; s < 8; s++) {
                const int kw = s * 8 + 2 * j;
                uint2 bf[4], lo[4], hi[4];
                #pragma unroll
                for (int nt = 0; nt < 4; nt++)
                    bf[nt] = *(const uint2*)&W1w[(n0 + nt * 8 + g) * SW + kw];
                #pragma unroll
                for (int mt = 0; mt < 4; mt++) {
                    lo[mt] = *(const uint2*)&Aw[(r0 + mt * 16 + g) * SW + kw];
                    hi[mt] = *(const uint2*)&Aw[(r0 + mt * 16 + 8 + g) * SW + kw];
                }
                #pragma unroll
                for (int mt = 0; mt < 4; mt++)
                    #pragma unroll
                    for (int nt = 0; nt < 4; nt++)
                        mma_f16(c[mt][nt], lo[mt].x, hi[mt].x, lo[mt].y, hi[mt].y,
                                bf[nt].x, bf[nt].y);
            }

            // ---- epilogue: h1 = softplus(D+b1); partial = h1 @ W2 via m16n8k16 ----
            float b1r[8];
            #pragma unroll
            for (int nt = 0; nt < 4; nt++) {
                b1r[nt * 2]     = b1s[n0 + nt * 8 + 2 * j];
                b1r[nt * 2 + 1] = b1s[n0 + nt * 8 + 2 * j + 1];
            }
            #pragma unroll
            for (int mt = 0; mt < 4; mt++) {
                float h[4][4];
                #pragma unroll
                for (int nt = 0; nt < 4; nt++) {
                    h[nt][0] = softplus_f(c[mt][nt][0] + b1r[nt * 2]);
                    h[nt][1] = softplus_f(c[mt][nt][1] + b1r[nt * 2 + 1]);
                    h[nt][2] = softplus_f(c[mt][nt][2] + b1r[nt * 2]);
                    h[nt][3] = softplus_f(c[mt][nt][3] + b1r[nt * 2 + 1]);
                }
                float d[4] = {0.f, 0.f, 0.f, 0.f};
                #pragma unroll
                for (int q = 0; q < 2; q++) {
                    uint32_t a0 = packh2(h[2 * q][0],     h[2 * q][1]);
                    uint32_t a1 = packh2(h[2 * q][2],     h[2 * q][3]);
                    uint32_t a2 = packh2(h[2 * q + 1][0], h[2 * q + 1][1]);
                    uint32_t a3 = packh2(h[2 * q + 1][2], h[2 * q + 1][3]);
                    mma_f16(d, a0, a1, a2, a3, w2f[q].x, w2f[q].y);
                }
                if (j < 2) {
                    int prow = ni * 128 + r0 + mt * 16 + g;
                    *(float2*)&P[prow * 4 + 2 * j]       = make_float2(d[0], d[1]);
                    *(float2*)&P[(prow + 8) * 4 + 2 * j] = make_float2(d[2], d[3]);
                }
            }
            asm volatile("bar.sync %0, 256;" :: "r"(wbar) : "memory");

            if (wt < 128) {
                const float4* P4 = (const float4*)P;
                float4 o4 = b2v;
                #pragma unroll
                for (int q = 0; q < 4; q++) {
                    float4 v = P4[q * 128 + wt];
                    o4.x += v.x; o4.y += v.y; o4.z += v.z; o4.w += v.w;
                }
                ((float4*)out)[rowBase + wt] = o4;
            }
            // no 4th barrier: Iw/P/Aw hazards are covered by bar1/bar2/bar3 of
            // the next iteration (inp no longer overlays P)
        }
        __syncthreads();   // both streams done before restaging weights
    }

    // ---- grid barrier ----
    __threadfence();
    __syncthreads();
    if (tid == 0) {
        unsigned int arrived = atomicAdd(&g_bar_count, 1) + 1;
        if (arrived == NCTA) {
            g_bar_count = 0;
            __threadfence();
            atomicAdd(&g_bar_sense, 1);
        } else {
            while (*(volatile unsigned int*)&g_bar_sense == sense0) { }
        }
    }
    __syncthreads();
    __threadfence();

    // ---- in-kernel reduce: out[n,rec,:] += sum_j scratch[n*90+rec*9+j,:] ----
    for (int r = blockIdx.x * NTHREADS + tid; r < SELF_ROWS; r += NCTA * NTHREADS) {
        int n = r / NBODY, rec = r - n * NBODY;
        const float4* sc = (const float4*)g_scratch;
        int base = n * NPAIRS + rec * (NBODY - 1);
        float4 s = sc[base];
        #pragma unroll
        for (int q = 1; q < NBODY - 1; q++) {
            float4 v = sc[base + q];
            s.x += v.x; s.y += v.y; s.z += v.z; s.w += v.w;
        }
        float4 o = ((float4*)out_self)[r];
        o.x += s.x; o.y += s.y; o.z += s.z; o.w += s.w;
        ((float4*)out_self)[r] = o;
    }
}

extern "C" void kernel_launch(void* const* d_in, const int* in_sizes, int n_in,
                              void* d_out, int out_size)
{
    const float* z   = (const float*)d_in[0];
    const float* fW0 = (const float*)d_in[1];
    const float* fb0 = (const float*)d_in[2];
    const float* fW1 = (const float*)d_in[3];
    const float* fb1 = (const float*)d_in[4];
    const float* fW2 = (const float*)d_in[5];
    const float* fb2 = (const float*)d_in[6];
    const float* iW0 = (const float*)d_in[7];
    const float* ib0 = (const float*)d_in[8];
    const float* iW1 = (const float*)d_in[9];
    const float* ib1 = (const float*)d_in[10];
    const float* iW2 = (const float*)d_in[11];
    const float* ib2 = (const float*)d_in[12];
    float* out = (float*)d_out;

    cudaFuncSetAttribute(mlp_all, cudaFuncAttributeMaxDynamicSharedMemorySize, SMEM_TOTAL);

    mlp_all<<<NCTA, NTHREADS, SMEM_TOTAL>>>(z, fW0, fb0, fW1, fb1, fW2, fb2,
                                            iW0, ib0, iW1, ib1, iW2, ib2, out);
}

// round 13
// speedup vs baseline: 1.5261x; 1.5261x over previous
#include <cuda_runtime.h>
#include <cuda_fp16.h>
#include <cstdint>

// ---------------- problem constants ----------------
#define NBODY     10
#define NPAIRS    90
#define HID       128
#define TILE      128
#define SELF_ROWS 81920
#define INT_ROWS  737280
#define SELF_TILES (SELF_ROWS / TILE)   // 640
#define INT_TILES  (INT_ROWS / TILE)    // 5760
#define NCTA      148
#define NTHREADS  512                   // 2 tile-streams of 256 threads
#define SW        72                    // Aw row stride in words (72%32=8, conflict-free)

// smem byte offsets
#define OFF_W1T   0          // 128 x SW half2-words                 36864 B
#define OFF_A0    36864      // stream 0 H0: 128 x SW half2-words    36864 B
#define OFF_A1    73728      // stream 1                             36864 B
#define OFF_P0    110592     // stream partials 8KB each
#define OFF_P1    118784
#define OFF_I0    126976     // stream packed inp: 128 x 8 words     4096 B each
#define OFF_I1    131072
#define OFF_W0H   135168     // W0 fp16 B-layout: 128 x 8 words      4096 B
#define OFF_W2H   139264     // W2 fp16 B-layout: 8 x 64 words       2048 B
#define OFF_B0    141312     // 128 fp32
#define OFF_B1    141824     // 128 fp32
#define OFF_B2    142336     // 4 fp32 (+pad)
#define SMEM_TOTAL 142368

__device__ float g_scratch[INT_ROWS * 4];
__device__ unsigned int g_bar_count = 0;
__device__ unsigned int g_bar_sense = 0;

// ---------------- helpers ----------------
__device__ __forceinline__ float softplus_f(float x) {
    float e = __expf(-fabsf(x));
    return fmaxf(x, 0.0f) + __logf(1.0f + e);
}
// permute words within each 8-group so (u, u+4) are adjacent -> uint2 loads
__device__ __forceinline__ int pos8(int c) {
    return (c & ~7) | ((c & 3) << 1) | ((c >> 2) & 1);
}
__device__ __forceinline__ uint32_t packh2(float a, float b) {
    __half2 v = __floats2half2_rn(a, b);
    return *(uint32_t*)&v;
}
__device__ __forceinline__ void mma_f16(float* c, uint32_t a0, uint32_t a1,
                                        uint32_t a2, uint32_t a3,
                                        uint32_t b0, uint32_t b1) {
    asm("mma.sync.aligned.m16n8k16.row.col.f32.f16.f16.f32 "
        "{%0,%1,%2,%3}, {%4,%5,%6,%7}, {%8,%9}, {%0,%1,%2,%3};"
        : "+f"(c[0]), "+f"(c[1]), "+f"(c[2]), "+f"(c[3])
        : "r"(a0), "r"(a1), "r"(a2), "r"(a3), "r"(b0), "r"(b1));
}

// ---------------- two-phase persistent fused MLP + in-kernel reduce ----------------
__global__ __launch_bounds__(NTHREADS, 1)
void mlp_all(const float* __restrict__ z,
             const float* __restrict__ fW0, const float* __restrict__ fb0,
             const float* __restrict__ fW1, const float* __restrict__ fb1,
             const float* __restrict__ fW2, const float* __restrict__ fb2,
             const float* __restrict__ iW0, const float* __restrict__ ib0,
             const float* __restrict__ iW1, const float* __restrict__ ib1,
             const float* __restrict__ iW2, const float* __restrict__ ib2,
             float* __restrict__ out_self)
{
    extern __shared__ __align__(16) char smem[];
    uint32_t* W1w = (uint32_t*)(smem + OFF_W1T);
    uint32_t* W0h = (uint32_t*)(smem + OFF_W0H);
    uint32_t* W2h = (uint32_t*)(smem + OFF_W2H);
    float*  b0s = (float*)(smem + OFF_B0);
    float*  b1s = (float*)(smem + OFF_B1);
    float*  b2s = (float*)(smem + OFF_B2);

    const int tid  = threadIdx.x;
    const int wg   = tid >> 8;            // tile stream 0/1
    const int wt   = tid & 255;
    const int w8   = wt >> 5;             // warp in stream: 0..7
    const int lane = tid & 31;
    const int g    = lane >> 2;
    const int j    = lane & 3;
    const int mi   = w8 >> 2;             // rows mi*64..+63
    const int ni   = w8 & 3;              // cols ni*32..+31

    uint32_t* Aw = (uint32_t*)(smem + OFF_A0 + wg * 36864);
    uint32_t* Iw = (uint32_t*)(smem + OFF_I0 + wg * 4096);
    float*    P  = (float*)(smem + OFF_P0 + wg * 8192);
    const int wbar = 1 + wg;

    // capture barrier sense for this launch
    __shared__ unsigned int sense0;
    if (tid == 0) sense0 = *(volatile unsigned int*)&g_bar_sense;
    __syncthreads();

    const int r0 = mi * 64, n0 = ni * 32;

    // Aw store positions for layer-0 output (word u = ni*16 + nt*4 + j)
    int apos[4];
    #pragma unroll
    for (int nt = 0; nt < 4; nt++) {
        int uu = ni * 16 + nt * 4 + j;
        apos[nt] = (uu & ~7) | ((uu & 3) << 1) | ((uu >> 2) & 1);
    }

    #pragma unroll 1
    for (int phase = 0; phase < 2; phase++) {
        const bool isSelf = (phase == 1);
        const float* W0 = isSelf ? fW0 : iW0;
        const float* b0 = isSelf ? fb0 : ib0;
        const float* W1 = isSelf ? fW1 : iW1;
        const float* b1 = isSelf ? fb1 : ib1;
        const float* W2 = isSelf ? fW2 : iW2;
        const float* b2 = isSelf ? fb2 : ib2;
        float* out = isSelf ? out_self : g_scratch;
        const int ntiles = isSelf ? SELF_TILES : INT_TILES;
        const int NIN = isSelf ? 4 : 6;

        // ---- stage weights for this phase ----
        for (int i = tid; i < 64 * HID; i += NTHREADS) {
            int uu = i >> 7, n = i & 127;
            W1w[n * SW + pos8(uu)] = packh2(W1[(2 * uu) * HID + n],
                                            W1[(2 * uu + 1) * HID + n]);
        }
        // W0h: word(n,u) = (W0[2u][n], W0[2u+1][n]) zero-padded, at n*8+pos8(u)
        for (int i = tid; i < 8 * HID; i += NTHREADS) {
            int n = i >> 3, uu = i & 7;
            float a = (2 * uu     < NIN) ? W0[(2 * uu)     * HID + n] : 0.0f;
            float b = (2 * uu + 1 < NIN) ? W0[(2 * uu + 1) * HID + n] : 0.0f;
            W0h[n * 8 + pos8(uu)] = packh2(a, b);
        }
        // W2h: word(n,u) = (W2[2u][n], W2[2u+1][n]) n<4 else 0, at n*64+pos8(u)
        for (int i = tid; i < 512; i += NTHREADS) {
            int n = i >> 6, uu = i & 63;
            float a = (n < 4) ? W2[(2 * uu)     * 4 + n] : 0.0f;
            float b = (n < 4) ? W2[(2 * uu + 1) * 4 + n] : 0.0f;
            W2h[n * 64 + pos8(uu)] = packh2(a, b);
        }
        if (tid < HID) { b0s[tid] = b0[tid]; b1s[tid] = b1[tid]; }
        if (tid < 4) b2s[tid] = b2[tid];
        __syncthreads();

        const float4 b2v = *(const float4*)b2s;
        // tile-invariant fragments
        uint2 w0f[4];
        #pragma unroll
        for (int nt = 0; nt < 4; nt++)
            w0f[nt] = *(const uint2*)&W0h[(n0 + nt * 8 + g) * 8 + 2 * j];
        uint2 w2f[2];
        #pragma unroll
        for (int q = 0; q < 2; q++)
            w2f[q] = *(const uint2*)&W2h[g * 64 + ni * 16 + 8 * q + 2 * j];
        float b0r[8];
        #pragma unroll
        for (int nt = 0; nt < 4; nt++) {
            b0r[nt * 2]     = b0s[n0 + nt * 8 + 2 * j];
            b0r[nt * 2 + 1] = b0s[n0 + nt * 8 + 2 * j + 1];
        }

        // ONLY change vs R11: reversed stream mapping in the self phase
        // balances per-CTA totals at <=44 tile-pairs (was 46 for low CTAs)
        int s0 = blockIdx.x * 2 + wg;
        if (isSelf) s0 = gridDim.x * 2 - 1 - s0;

        for (int t = s0; t < ntiles; t += gridDim.x * 2) {
            const int rowBase = t * TILE;

            // ---- build 128 packed input rows (fp16) ----
            if (wt < 128) {
                int grow = rowBase + wt;
                uint32_t wA, wB, wC;
                if (isSelf) {
                    float4 zz = ((const float4*)z)[grow];
                    wA = packh2(zz.x, zz.y); wB = packh2(zz.z, zz.w); wC = 0u;
                } else {
                    int n   = grow / NPAIRS;
                    int pr  = grow - n * NPAIRS;
                    int rec = pr / (NBODY - 1);
                    int sr  = pr - rec * (NBODY - 1);
                    int snd = sr + (sr >= rec ? 1 : 0);
                    float4 zr = ((const float4*)z)[n * NBODY + rec];
                    float4 zs = ((const float4*)z)[n * NBODY + snd];
                    wA = packh2(zr.x - zs.x, zr.y - zs.y);
                    wB = packh2(zr.z, zr.w);
                    wC = packh2(zs.z, zs.w);
                }
                int base = wt * 8;
                *(uint2*)&Iw[base + 0] = make_uint2(wA, 0u);
                *(uint2*)&Iw[base + 2] = make_uint2(wB, 0u);
                *(uint2*)&Iw[base + 4] = make_uint2(wC, 0u);
                *(uint2*)&Iw[base + 6] = make_uint2(0u, 0u);
            }
            asm volatile("bar.sync %0, 256;" :: "r"(wbar) : "memory");

            float c[4][4][4];

            // ---- layer 0 via m16n8k16: preact = inp @ W0 ----
            #pragma unroll
            for (int mt = 0; mt < 4; mt++)
                #pragma unroll
                for (int nt = 0; nt < 4; nt++)
                    #pragma unroll
                    for (int q = 0; q < 4; q++) c[mt][nt][q] = 0.0f;
            #pragma unroll
            for (int mt = 0; mt < 4; mt++) {
                uint2 lo = *(const uint2*)&Iw[(r0 + mt * 16 + g) * 8 + 2 * j];
                uint2 hi = *(const uint2*)&Iw[(r0 + mt * 16 + 8 + g) * 8 + 2 * j];
                #pragma unroll
                for (int nt = 0; nt < 4; nt++)
                    mma_f16(c[mt][nt], lo.x, hi.x, lo.y, hi.y,
                            w0f[nt].x, w0f[nt].y);
            }
            // softplus + pack + store H0 slice (rows r0..r0+63, cols n0..n0+31)
            #pragma unroll
            for (int mt = 0; mt < 4; mt++)
                #pragma unroll
                for (int nt = 0; nt < 4; nt++) {
                    float p0 = softplus_f(c[mt][nt][0] + b0r[nt * 2]);
                    float p1 = softplus_f(c[mt][nt][1] + b0r[nt * 2 + 1]);
                    float p2 = softplus_f(c[mt][nt][2] + b0r[nt * 2]);
                    float p3 = softplus_f(c[mt][nt][3] + b0r[nt * 2 + 1]);
                    Aw[(r0 + mt * 16 + g) * SW + apos[nt]]     = packh2(p0, p1);
                    Aw[(r0 + mt * 16 + 8 + g) * SW + apos[nt]] = packh2(p2, p3);
                }
            asm volatile("bar.sync %0, 256;" :: "r"(wbar) : "memory");

            // ---- layer 1: 64x32 warp tile, m16n8k16 fp16, 8 k-steps (R8-exact) ----
            #pragma unroll
            for (int mt = 0; mt < 4; mt++)
                #pragma unroll
                for (int nt = 0; nt < 4; nt++)
                    #pragma unroll
                    for (int q = 0; q < 4; q++) c[mt][nt][q] = 0.0f;

            #pragma unroll 1
            for (int s = 0; s < 8; s++) {
                const int kw = s * 8 + 2 * j;
                uint2 bf[4], lo[4], hi[4];
                #pragma unroll
                for (int nt = 0; nt < 4; nt++)
                    bf[nt] = *(const uint2*)&W1w[(n0 + nt * 8 + g) * SW + kw];
                #pragma unroll
                for (int mt = 0; mt < 4; mt++) {
                    lo[mt] = *(const uint2*)&Aw[(r0 + mt * 16 + g) * SW + kw];
                    hi[mt] = *(const uint2*)&Aw[(r0 + mt * 16 + 8 + g) * SW + kw];
                }
                #pragma unroll
                for (int mt = 0; mt < 4; mt++)
                    #pragma unroll
                    for (int nt = 0; nt < 4; nt++)
                        mma_f16(c[mt][nt], lo[mt].x, hi[mt].x, lo[mt].y, hi[mt].y,
                                bf[nt].x, bf[nt].y);
            }

            // ---- epilogue: h1 = softplus(D+b1); partial = h1 @ W2 via m16n8k16 ----
            float b1r[8];
            #pragma unroll
            for (int nt = 0; nt < 4; nt++) {
                b1r[nt * 2]     = b1s[n0 + nt * 8 + 2 * j];
                b1r[nt * 2 + 1] = b1s[n0 + nt * 8 + 2 * j + 1];
            }
            #pragma unroll
            for (int mt = 0; mt < 4; mt++) {
                float h[4][4];
                #pragma unroll
                for (int nt = 0; nt < 4; nt++) {
                    h[nt][0] = softplus_f(c[mt][nt][0] + b1r[nt * 2]);
                    h[nt][1] = softplus_f(c[mt][nt][1] + b1r[nt * 2 + 1]);
                    h[nt][2] = softplus_f(c[mt][nt][2] + b1r[nt * 2]);
                    h[nt][3] = softplus_f(c[mt][nt][3] + b1r[nt * 2 + 1]);
                }
                float d[4] = {0.f, 0.f, 0.f, 0.f};
                #pragma unroll
                for (int q = 0; q < 2; q++) {
                    uint32_t a0 = packh2(h[2 * q][0],     h[2 * q][1]);
                    uint32_t a1 = packh2(h[2 * q][2],     h[2 * q][3]);
                    uint32_t a2 = packh2(h[2 * q + 1][0], h[2 * q + 1][1]);
                    uint32_t a3 = packh2(h[2 * q + 1][2], h[2 * q + 1][3]);
                    mma_f16(d, a0, a1, a2, a3, w2f[q].x, w2f[q].y);
                }
                if (j < 2) {
                    int prow = ni * 128 + r0 + mt * 16 + g;
                    *(float2*)&P[prow * 4 + 2 * j]       = make_float2(d[0], d[1]);
                    *(float2*)&P[(prow + 8) * 4 + 2 * j] = make_float2(d[2], d[3]);
                }
            }
            asm volatile("bar.sync %0, 256;" :: "r"(wbar) : "memory");

            if (wt < 128) {
                const float4* P4 = (const float4*)P;
                float4 o4 = b2v;
                #pragma unroll
                for (int q = 0; q < 4; q++) {
                    float4 v = P4[q * 128 + wt];
                    o4.x += v.x; o4.y += v.y; o4.z += v.z; o4.w += v.w;
                }
                ((float4*)out)[rowBase + wt] = o4;
            }
            asm volatile("bar.sync %0, 256;" :: "r"(wbar) : "memory");
        }
        __syncthreads();   // both streams done before restaging weights
    }

    // ---- grid barrier ----
    __threadfence();
    __syncthreads();
    if (tid == 0) {
        unsigned int arrived = atomicAdd(&g_bar_count, 1) + 1;
        if (arrived == NCTA) {
            g_bar_count = 0;
            __threadfence();
            atomicAdd(&g_bar_sense, 1);
        } else {
            while (*(volatile unsigned int*)&g_bar_sense == sense0) { }
        }
    }
    __syncthreads();
    __threadfence();

    // ---- in-kernel reduce: out[n,rec,:] += sum_j scratch[n*90+rec*9+j,:] ----
    for (int r = blockIdx.x * NTHREADS + tid; r < SELF_ROWS; r += NCTA * NTHREADS) {
        int n = r / NBODY, rec = r - n * NBODY;
        const float4* sc = (const float4*)g_scratch;
        int base = n * NPAIRS + rec * (NBODY - 1);
        float4 s = sc[base];
        #pragma unroll
        for (int q = 1; q < NBODY - 1; q++) {
            float4 v = sc[base + q];
            s.x += v.x; s.y += v.y; s.z += v.z; s.w += v.w;
        }
        float4 o = ((float4*)out_self)[r];
        o.x += s.x; o.y += s.y; o.z += s.z; o.w += s.w;
        ((float4*)out_self)[r] = o;
    }
}

extern "C" void kernel_launch(void* const* d_in, const int* in_sizes, int n_in,
                              void* d_out, int out_size)
{
    const float* z   = (const float*)d_in[0];
    const float* fW0 = (const float*)d_in[1];
    const float* fb0 = (const float*)d_in[2];
    const float* fW1 = (const float*)d_in[3];
    const float* fb1 = (const float*)d_in[4];
    const float* fW2 = (const float*)d_in[5];
    const float* fb2 = (const float*)d_in[6];
    const float* iW0 = (const float*)d_in[7];
    const float* ib0 = (const float*)d_in[8];
    const float* iW1 = (const float*)d_in[9];
    const float* ib1 = (const float*)d_in[10];
    const float* iW2 = (const float*)d_in[11];
    const float* ib2 = (const float*)d_in[12];
    float* out = (float*)d_out;

    cudaFuncSetAttribute(mlp_all, cudaFuncAttributeMaxDynamicSharedMemorySize, SMEM_TOTAL);

    mlp_all<<<NCTA, NTHREADS, SMEM_TOTAL>>>(z, fW0, fb0, fW1, fb1, fW2, fb2,
                                            iW0, ib0, iW1, ib1, iW2, ib2, out);
}

// round 14
// speedup vs baseline: 1.5506x; 1.0160x over previous
#include <cuda_runtime.h>
#include <cuda_fp16.h>
#include <cstdint>

// ---------------- problem constants ----------------
#define NBODY     10
#define NPAIRS    90
#define HID       128
#define TILE      128
#define SELF_ROWS 81920
#define INT_ROWS  737280
#define SELF_TILES (SELF_ROWS / TILE)   // 640
#define INT_TILES  (INT_ROWS / TILE)    // 5760
#define NCTA      148
#define NTHREADS  512                   // 2 tile-streams of 256 threads
#define SW        72                    // Aw row stride in words (72%32=8, conflict-free)

// smem byte offsets
#define OFF_W1T   0          // 128 x SW half2-words                 36864 B
#define OFF_A0    36864      // stream 0 H0: 128 x SW half2-words    36864 B
#define OFF_A1    73728      // stream 1                             36864 B
#define OFF_P0    110592     // stream partials 8KB each
#define OFF_P1    118784
#define OFF_I0    126976     // stream packed inp: 128 x 8 words     4096 B each
#define OFF_I1    131072
#define OFF_W0H   135168     // W0 fp16 B-layout (+b0 in word 7): 128 x 8 words
#define OFF_W2H   139264     // W2 fp16 B-layout: 8 x 64 words       2048 B
#define OFF_B1    141312     // 128 fp32
#define OFF_B2    141824     // 4 fp32 (+pad)
#define SMEM_TOTAL 141856

#define ONE_H2    0x00003C00u   // half2 (1.0, 0.0) -> k14 = 1.0 bias lane

__device__ float g_scratch[INT_ROWS * 4];
__device__ unsigned int g_bar_count = 0;
__device__ unsigned int g_bar_sense = 0;

// ---------------- helpers ----------------
__device__ __forceinline__ float softplus_f(float x) {
    float e = __expf(-fabsf(x));
    return fmaxf(x, 0.0f) + __logf(1.0f + e);
}
// permute words within each 8-group so (u, u+4) are adjacent -> uint2 loads
__device__ __forceinline__ int pos8(int c) {
    return (c & ~7) | ((c & 3) << 1) | ((c >> 2) & 1);
}
__device__ __forceinline__ uint32_t packh2(float a, float b) {
    __half2 v = __floats2half2_rn(a, b);
    return *(uint32_t*)&v;
}
__device__ __forceinline__ void mma_f16(float* c, uint32_t a0, uint32_t a1,
                                        uint32_t a2, uint32_t a3,
                                        uint32_t b0, uint32_t b1) {
    asm("mma.sync.aligned.m16n8k16.row.col.f32.f16.f16.f32 "
        "{%0,%1,%2,%3}, {%4,%5,%6,%7}, {%8,%9}, {%0,%1,%2,%3};"
        : "+f"(c[0]), "+f"(c[1]), "+f"(c[2]), "+f"(c[3])
        : "r"(a0), "r"(a1), "r"(a2), "r"(a3), "r"(b0), "r"(b1));
}

// ---------------- two-phase persistent fused MLP + in-kernel reduce ----------------
__global__ __launch_bounds__(NTHREADS, 1)
void mlp_all(const float* __restrict__ z,
             const float* __restrict__ fW0, const float* __restrict__ fb0,
             const float* __restrict__ fW1, const float* __restrict__ fb1,
             const float* __restrict__ fW2, const float* __restrict__ fb2,
             const float* __restrict__ iW0, const float* __restrict__ ib0,
             const float* __restrict__ iW1, const float* __restrict__ ib1,
             const float* __restrict__ iW2, const float* __restrict__ ib2,
             float* __restrict__ out_self)
{
    extern __shared__ __align__(16) char smem[];
    uint32_t* W1w = (uint32_t*)(smem + OFF_W1T);
    uint32_t* W0h = (uint32_t*)(smem + OFF_W0H);
    uint32_t* W2h = (uint32_t*)(smem + OFF_W2H);
    float*  b1s = (float*)(smem + OFF_B1);
    float*  b2s = (float*)(smem + OFF_B2);

    const int tid  = threadIdx.x;
    const int wg   = tid >> 8;            // tile stream 0/1
    const int wt   = tid & 255;
    const int w8   = wt >> 5;             // warp in stream: 0..7
    const int lane = tid & 31;
    const int g    = lane >> 2;
    const int j    = lane & 3;
    const int mi   = w8 >> 2;             // rows mi*64..+63
    const int ni   = w8 & 3;              // cols ni*32..+31

    uint32_t* Aw = (uint32_t*)(smem + OFF_A0 + wg * 36864);
    uint32_t* Iw = (uint32_t*)(smem + OFF_I0 + wg * 4096);
    float*    P  = (float*)(smem + OFF_P0 + wg * 8192);
    const int wbar = 1 + wg;

    // capture barrier sense for this launch
    __shared__ unsigned int sense0;
    if (tid == 0) sense0 = *(volatile unsigned int*)&g_bar_sense;
    __syncthreads();

    const int r0 = mi * 64, n0 = ni * 32;

    // Aw store positions for layer-0 output (word u = ni*16 + nt*4 + j)
    int apos[4];
    #pragma unroll
    for (int nt = 0; nt < 4; nt++) {
        int uu = ni * 16 + nt * 4 + j;
        apos[nt] = (uu & ~7) | ((uu & 3) << 1) | ((uu >> 2) & 1);
    }

    #pragma unroll 1
    for (int phase = 0; phase < 2; phase++) {
        const bool isSelf = (phase == 1);
        const float* W0 = isSelf ? fW0 : iW0;
        const float* b0 = isSelf ? fb0 : ib0;
        const float* W1 = isSelf ? fW1 : iW1;
        const float* b1 = isSelf ? fb1 : ib1;
        const float* W2 = isSelf ? fW2 : iW2;
        const float* b2 = isSelf ? fb2 : ib2;
        float* out = isSelf ? out_self : g_scratch;
        const int ntiles = isSelf ? SELF_TILES : INT_TILES;
        const int NIN = isSelf ? 4 : 6;

        // ---- stage weights for this phase ----
        for (int i = tid; i < 64 * HID; i += NTHREADS) {
            int uu = i >> 7, n = i & 127;
            W1w[n * SW + pos8(uu)] = packh2(W1[(2 * uu) * HID + n],
                                            W1[(2 * uu + 1) * HID + n]);
        }
        // W0h: word(n,u) = (W0[2u][n], W0[2u+1][n]) zero-padded; word 7 = (b0[n], 0)
        for (int i = tid; i < 8 * HID; i += NTHREADS) {
            int n = i >> 3, uu = i & 7;
            float a, b;
            if (uu == 7) { a = b0[n]; b = 0.0f; }
            else {
                a = (2 * uu     < NIN) ? W0[(2 * uu)     * HID + n] : 0.0f;
                b = (2 * uu + 1 < NIN) ? W0[(2 * uu + 1) * HID + n] : 0.0f;
            }
            W0h[n * 8 + pos8(uu)] = packh2(a, b);
        }
        // W2h: word(n,u) = (W2[2u][n], W2[2u+1][n]) n<4 else 0, at n*64+pos8(u)
        for (int i = tid; i < 512; i += NTHREADS) {
            int n = i >> 6, uu = i & 63;
            float a = (n < 4) ? W2[(2 * uu)     * 4 + n] : 0.0f;
            float b = (n < 4) ? W2[(2 * uu + 1) * 4 + n] : 0.0f;
            W2h[n * 64 + pos8(uu)] = packh2(a, b);
        }
        if (tid < HID) b1s[tid] = b1[tid];
        if (tid < 4) b2s[tid] = b2[tid];
        __syncthreads();

        const float4 b2v = *(const float4*)b2s;
        // tile-invariant fragments
        uint2 w0f[4];
        #pragma unroll
        for (int nt = 0; nt < 4; nt++)
            w0f[nt] = *(const uint2*)&W0h[(n0 + nt * 8 + g) * 8 + 2 * j];
        uint2 w2f[2];
        #pragma unroll
        for (int q = 0; q < 2; q++)
            w2f[q] = *(const uint2*)&W2h[g * 64 + ni * 16 + 8 * q + 2 * j];

        // reversed stream mapping in the self phase balances per-CTA totals <=44
        int s0 = blockIdx.x * 2 + wg;
        if (isSelf) s0 = gridDim.x * 2 - 1 - s0;

        for (int t = s0; t < ntiles; t += gridDim.x * 2) {
            const int rowBase = t * TILE;

            // ---- build 128 packed input rows (fp16); k14 = 1.0 (bias lane) ----
            if (wt < 128) {
                int grow = rowBase + wt;
                uint32_t wA, wB, wC;
                if (isSelf) {
                    float4 zz = ((const float4*)z)[grow];
                    wA = packh2(zz.x, zz.y); wB = packh2(zz.z, zz.w); wC = 0u;
                } else {
                    int n   = grow / NPAIRS;
                    int pr  = grow - n * NPAIRS;
                    int rec = pr / (NBODY - 1);
                    int sr  = pr - rec * (NBODY - 1);
                    int snd = sr + (sr >= rec ? 1 : 0);
                    float4 zr = ((const float4*)z)[n * NBODY + rec];
                    float4 zs = ((const float4*)z)[n * NBODY + snd];
                    wA = packh2(zr.x - zs.x, zr.y - zs.y);
                    wB = packh2(zr.z, zr.w);
                    wC = packh2(zs.z, zs.w);
                }
                int base = wt * 8;
                *(uint2*)&Iw[base + 0] = make_uint2(wA, 0u);
                *(uint2*)&Iw[base + 2] = make_uint2(wB, 0u);
                *(uint2*)&Iw[base + 4] = make_uint2(wC, 0u);
                *(uint2*)&Iw[base + 6] = make_uint2(0u, ONE_H2);
            }
            asm volatile("bar.sync %0, 256;" :: "r"(wbar) : "memory");

            float c[4][4][4];

            // ---- layer 0 via m16n8k16: preact = inp @ W0 + b0 (k14 lane) ----
            #pragma unroll
            for (int mt = 0; mt < 4; mt++)
                #pragma unroll
                for (int nt = 0; nt < 4; nt++)
                    #pragma unroll
                    for (int q = 0; q < 4; q++) c[mt][nt][q] = 0.0f;
            #pragma unroll
            for (int mt = 0; mt < 4; mt++) {
                uint2 lo = *(const uint2*)&Iw[(r0 + mt * 16 + g) * 8 + 2 * j];
                uint2 hi = *(const uint2*)&Iw[(r0 + mt * 16 + 8 + g) * 8 + 2 * j];
                #pragma unroll
                for (int nt = 0; nt < 4; nt++)
                    mma_f16(c[mt][nt], lo.x, hi.x, lo.y, hi.y,
                            w0f[nt].x, w0f[nt].y);
            }
            // softplus + pack + store H0 slice (rows r0..r0+63, cols n0..n0+31)
            #pragma unroll
            for (int mt = 0; mt < 4; mt++)
                #pragma unroll
                for (int nt = 0; nt < 4; nt++) {
                    float p0 = softplus_f(c[mt][nt][0]);
                    float p1 = softplus_f(c[mt][nt][1]);
                    float p2 = softplus_f(c[mt][nt][2]);
                    float p3 = softplus_f(c[mt][nt][3]);
                    Aw[(r0 + mt * 16 + g) * SW + apos[nt]]     = packh2(p0, p1);
                    Aw[(r0 + mt * 16 + 8 + g) * SW + apos[nt]] = packh2(p2, p3);
                }
            asm volatile("bar.sync %0, 256;" :: "r"(wbar) : "memory");

            // ---- layer 1: 64x32 warp tile, m16n8k16 fp16, 8 k-steps (R8-exact) ----
            #pragma unroll
            for (int mt = 0; mt < 4; mt++)
                #pragma unroll
                for (int nt = 0; nt < 4; nt++)
                    #pragma unroll
                    for (int q = 0; q < 4; q++) c[mt][nt][q] = 0.0f;

            #pragma unroll 1
            for (int s = 0; s < 8; s++) {
                const int kw = s * 8 + 2 * j;
                uint2 bf[4], lo[4], hi[4];
                #pragma unroll
                for (int nt = 0; nt < 4; nt++)
                    bf[nt] = *(const uint2*)&W1w[(n0 + nt * 8 + g) * SW + kw];
                #pragma unroll
                for (int mt = 0; mt < 4; mt++) {
                    lo[mt] = *(const uint2*)&Aw[(r0 + mt * 16 + g) * SW + kw];
                    hi[mt] = *(const uint2*)&Aw[(r0 + mt * 16 + 8 + g) * SW + kw];
                }
                #pragma unroll
                for (int mt = 0; mt < 4; mt++)
                    #pragma unroll
                    for (int nt = 0; nt < 4; nt++)
                        mma_f16(c[mt][nt], lo[mt].x, hi[mt].x, lo[mt].y, hi[mt].y,
                                bf[nt].x, bf[nt].y);
            }

            // ---- epilogue: h1 = softplus(D+b1); partial = h1 @ W2 via m16n8k16 ----
            float b1r[8];
            #pragma unroll
            for (int nt = 0; nt < 4; nt++) {
                b1r[nt * 2]     = b1s[n0 + nt * 8 + 2 * j];
                b1r[nt * 2 + 1] = b1s[n0 + nt * 8 + 2 * j + 1];
            }
            #pragma unroll
            for (int mt = 0; mt < 4; mt++) {
                float h[4][4];
                #pragma unroll
                for (int nt = 0; nt < 4; nt++) {
                    h[nt][0] = softplus_f(c[mt][nt][0] + b1r[nt * 2]);
                    h[nt][1] = softplus_f(c[mt][nt][1] + b1r[nt * 2 + 1]);
                    h[nt][2] = softplus_f(c[mt][nt][2] + b1r[nt * 2]);
                    h[nt][3] = softplus_f(c[mt][nt][3] + b1r[nt * 2 + 1]);
                }
                float d[4] = {0.f, 0.f, 0.f, 0.f};
                #pragma unroll
                for (int q = 0; q < 2; q++) {
                    uint32_t a0 = packh2(h[2 * q][0],     h[2 * q][1]);
                    uint32_t a1 = packh2(h[2 * q][2],     h[2 * q][3]);
                    uint32_t a2 = packh2(h[2 * q + 1][0], h[2 * q + 1][1]);
                    uint32_t a3 = packh2(h[2 * q + 1][2], h[2 * q + 1][3]);
                    mma_f16(d, a0, a1, a2, a3, w2f[q].x, w2f[q].y);
                }
                if (j < 2) {
                    int prow = ni * 128 + r0 + mt * 16 + g;
                    *(float2*)&P[prow * 4 + 2 * j]       = make_float2(d[0], d[1]);
                    *(float2*)&P[(prow + 8) * 4 + 2 * j] = make_float2(d[2], d[3]);
                }
            }
            asm volatile("bar.sync %0, 256;" :: "r"(wbar) : "memory");

            if (wt < 128) {
                const float4* P4 = (const float4*)P;
                float4 o4 = b2v;
                #pragma unroll
                for (int q = 0; q < 4; q++) {
                    float4 v = P4[q * 128 + wt];
                    o4.x += v.x; o4.y += v.y; o4.z += v.z; o4.w += v.w;
                }
                ((float4*)out)[rowBase + wt] = o4;
            }
            asm volatile("bar.sync %0, 256;" :: "r"(wbar) : "memory");
        }
        __syncthreads();   // both streams done before restaging weights
    }

    // ---- grid barrier ----
    __threadfence();
    __syncthreads();
    if (tid == 0) {
        unsigned int arrived = atomicAdd(&g_bar_count, 1) + 1;
        if (arrived == NCTA) {
            g_bar_count = 0;
            __threadfence();
            atomicAdd(&g_bar_sense, 1);
        } else {
            while (*(volatile unsigned int*)&g_bar_sense == sense0) { }
        }
    }
    __syncthreads();
    __threadfence();

    // ---- in-kernel reduce: out[n,rec,:] += sum_j scratch[n*90+rec*9+j,:] ----
    for (int r = blockIdx.x * NTHREADS + tid; r < SELF_ROWS; r += NCTA * NTHREADS) {
        int n = r / NBODY, rec = r - n * NBODY;
        const float4* sc = (const float4*)g_scratch;
        int base = n * NPAIRS + rec * (NBODY - 1);
        float4 s = sc[base];
        #pragma unroll
        for (int q = 1; q < NBODY - 1; q++) {
            float4 v = sc[base + q];
            s.x += v.x; s.y += v.y; s.z += v.z; s.w += v.w;
        }
        float4 o = ((float4*)out_self)[r];
        o.x += s.x; o.y += s.y; o.z += s.z; o.w += s.w;
        ((float4*)out_self)[r] = o;
    }
}

extern "C" void kernel_launch(void* const* d_in, const int* in_sizes, int n_in,
                              void* d_out, int out_size)
{
    const float* z   = (const float*)d_in[0];
    const float* fW0 = (const float*)d_in[1];
    const float* fb0 = (const float*)d_in[2];
    const float* fW1 = (const float*)d_in[3];
    const float* fb1 = (const float*)d_in[4];
    const float* fW2 = (const float*)d_in[5];
    const float* fb2 = (const float*)d_in[6];
    const float* iW0 = (const float*)d_in[7];
    const float* ib0 = (const float*)d_in[8];
    const float* iW1 = (const float*)d_in[9];
    const float* ib1 = (const float*)d_in[10];
    const float* iW2 = (const float*)d_in[11];
    const float* ib2 = (const float*)d_in[12];
    float* out = (float*)d_out;

    cudaFuncSetAttribute(mlp_all, cudaFuncAttributeMaxDynamicSharedMemorySize, SMEM_TOTAL);

    mlp_all<<<NCTA, NTHREADS, SMEM_TOTAL>>>(z, fW0, fb0, fW1, fb1, fW2, fb2,
                                            iW0, ib0, iW1, ib1, iW2, ib2, out);
}